// round 6
// baseline (speedup 1.0000x reference)
#include <cuda_runtime.h>

#define NN        16384
#define INF       256
#define OUTF      128
#define GEMM_CTAS 512          // producers: bids 0..511, 32 HW rows each
#define GRID      1184         // 148 SMs x 8 CTAs, all resident at occ 8
#define CAP       256          // per-row nnz cap (mean 32.8, sigma 5.7)
#define BUF       16           // rows buffered per CTA while GEMM pending

__device__ float        g_HW[NN * OUTF];   // HW = H @ W^T (8 MB, L2-resident)
__device__ unsigned int g_done = 0;        // producer CTAs finished
__device__ unsigned int g_row  = 0;        // scan-row work queue
__device__ unsigned int g_fin  = 0;        // retired CTAs (self-reset)

struct GemmSm {                            // 19.0 KB
    float hS[16][33];
    float kS[32][OUTF + 4];
};
struct AggSm {                             // ~17 KB
    int   idx[BUF][CAP];
    int   cnt[BUF];
    int   rowid[BUF];
    float red[OUTF];
    int   next;
    int   rdy;
};
union SmU { GemmSm g; AggSm a; };

__global__ __launch_bounds__(256, 8) void gcn_fused(const float* __restrict__ A,
                                                    const float* __restrict__ H,
                                                    const float* __restrict__ W,
                                                    float* __restrict__ out) {
    __shared__ SmU sm;
    const int tid = threadIdx.x;
    const int bid = blockIdx.x;

    // ======== Phase 0 (bids 0..511): 32 rows of HW, two 16-row tiles =======
    if (bid < GEMM_CTAS) {
        const int tc  = tid & 31;          // col group: cols [tc*4, tc*4+3]
        const int trw = tid >> 5;          // row group: rows trw*2, trw*2+1
        for (int tile = 0; tile < 2; tile++) {
            const int row0 = bid * 32 + tile * 16;
            float4 acc0 = make_float4(0.f, 0.f, 0.f, 0.f);
            float4 acc1 = make_float4(0.f, 0.f, 0.f, 0.f);

            for (int k0 = 0; k0 < INF; k0 += 32) {
#pragma unroll
                for (int p = 0; p < 2; p++) {          // H tile 16x32
                    int idx = p * 256 + tid;
                    int r = idx >> 5, kk = idx & 31;
                    sm.g.hS[r][kk] = H[(size_t)(row0 + r) * INF + k0 + kk];
                }
#pragma unroll
                for (int p = 0; p < 16; p++) {         // W tile 32k x 128o
                    int idx = p * 256 + tid;
                    int o = idx >> 5, kk = idx & 31;
                    sm.g.kS[kk][o] = W[(size_t)o * INF + k0 + kk];
                }
                __syncthreads();
#pragma unroll
                for (int kk = 0; kk < 32; kk++) {
                    float4 b = *(const float4*)&sm.g.kS[kk][tc * 4];
                    float a0 = sm.g.hS[trw * 2 + 0][kk];   // warp broadcast
                    float a1 = sm.g.hS[trw * 2 + 1][kk];
                    acc0.x += a0 * b.x; acc0.y += a0 * b.y;
                    acc0.z += a0 * b.z; acc0.w += a0 * b.w;
                    acc1.x += a1 * b.x; acc1.y += a1 * b.y;
                    acc1.z += a1 * b.z; acc1.w += a1 * b.w;
                }
                __syncthreads();
            }
            *(float4*)&g_HW[(size_t)(row0 + trw * 2 + 0) * OUTF + tc * 4] = acc0;
            *(float4*)&g_HW[(size_t)(row0 + trw * 2 + 1) * OUTF + tc * 4] = acc1;
        }
        __syncthreads();
        __threadfence();
        if (tid == 0) atomicAdd(&g_done, 1u);
        __syncthreads();   // smem union handoff (gemm -> agg)
    }

    // ======== Phase 1: persistent scan+gather via work queue ===============
    const int c = tid & 127;     // output column
    const int h = tid >> 7;      // half: alternate neighbors
    bool ready = false;
    int  nbuf  = 0;

    for (;;) {
        if (tid == 0) {
            sm.a.next = (int)atomicAdd(&g_row, 1u);
            sm.a.cnt[nbuf] = 0;
        }
        __syncthreads();
        const int row = sm.a.next;
        if (row >= NN) break;
        if (tid == 0) sm.a.rowid[nbuf] = row;

        // ---- scan A[row,:]: depth-4 batched loads, then rare nnz handling --
        const float4* Arow = (const float4*)(A + (size_t)row * NN);
        int* slot = sm.a.idx[nbuf];
        int* scnt = &sm.a.cnt[nbuf];
#pragma unroll
        for (int it = 0; it < 4; it++) {
            const int q0 = it * 1024 + tid;          // float4 index base
            float4 v0 = __ldcs(&Arow[q0]);           // 4 independent LDG.128s
            float4 v1 = __ldcs(&Arow[q0 + 256]);     // -> front-batched, MLP=4
            float4 v2 = __ldcs(&Arow[q0 + 512]);
            float4 v3 = __ldcs(&Arow[q0 + 768]);
#define EMIT(vv, qq)                                                            \
            do {                                                                \
                int base = (qq) * 4;                                            \
                if ((vv).x != 0.f) { int p = atomicAdd(scnt, 1); if (p < CAP) slot[p] = base;     } \
                if ((vv).y != 0.f) { int p = atomicAdd(scnt, 1); if (p < CAP) slot[p] = base + 1; } \
                if ((vv).z != 0.f) { int p = atomicAdd(scnt, 1); if (p < CAP) slot[p] = base + 2; } \
                if ((vv).w != 0.f) { int p = atomicAdd(scnt, 1); if (p < CAP) slot[p] = base + 3; } \
            } while (0)
            EMIT(v0, q0);
            EMIT(v1, q0 + 256);
            EMIT(v2, q0 + 512);
            EMIT(v3, q0 + 768);
#undef EMIT
        }
        __syncthreads();

        // ---- is HW ready yet? ----
        if (!ready) {
            if (tid == 0) {
                sm.a.rdy = (atomicAdd(&g_done, 0u) >= GEMM_CTAS);
                if (sm.a.rdy) __threadfence();           // acquire g_HW
            }
            __syncthreads();
            ready = (sm.a.rdy != 0);
        }

        if (ready || nbuf == BUF - 1) {
            if (!ready) {                                 // buffers full: wait
                if (tid == 0) {
                    while (atomicAdd(&g_done, 0u) < GEMM_CTAS) __nanosleep(64);
                    __threadfence();
                }
                __syncthreads();
                ready = true;
            }
            // ---- gather + write all buffered rows ----
            for (int s = 0; s <= nbuf; s++) {
                const int cnt = sm.a.cnt[s];
                const int lim = cnt < CAP ? cnt : CAP;
                float acc = 0.f;
#pragma unroll 4
                for (int k = h; k < lim; k += 2)
                    acc += g_HW[(size_t)sm.a.idx[s][k] * OUTF + c];  // L2 hit
                if (h) sm.a.red[c] = acc;
                __syncthreads();
                if (!h)
                    out[(size_t)sm.a.rowid[s] * OUTF + c] =
                        (acc + sm.a.red[c]) / (float)(cnt + 1);
                __syncthreads();
            }
            nbuf = 0;
        } else {
            nbuf++;
        }
        __syncthreads();
    }

    // ---- flush leftover buffered rows ----
    if (nbuf > 0) {
        if (tid == 0) {
            while (atomicAdd(&g_done, 0u) < GEMM_CTAS) __nanosleep(64);
            __threadfence();
        }
        __syncthreads();
        for (int s = 0; s < nbuf; s++) {
            const int cnt = sm.a.cnt[s];
            const int lim = cnt < CAP ? cnt : CAP;
            float acc = 0.f;
#pragma unroll 4
            for (int k = h; k < lim; k += 2)
                acc += g_HW[(size_t)sm.a.idx[s][k] * OUTF + c];
            if (h) sm.a.red[c] = acc;
            __syncthreads();
            if (!h)
                out[(size_t)sm.a.rowid[s] * OUTF + c] =
                    (acc + sm.a.red[c]) / (float)(cnt + 1);
            __syncthreads();
        }
    }

    // ---- self-reset of globals by last-retiring CTA (graph-replay safe) ----
    if (tid == 0) {
        unsigned t = atomicAdd(&g_fin, 1u);
        if (t == (unsigned)(gridDim.x - 1)) {
            g_done = 0;
            g_row  = 0;
            g_fin  = 0;
            __threadfence();
        }
    }
}

extern "C" void kernel_launch(void* const* d_in, const int* in_sizes, int n_in,
                              void* d_out, int out_size) {
    const float* A = (const float*)d_in[0];   // [16384, 16384]
    const float* H = (const float*)d_in[1];   // [16384, 256]
    const float* W = (const float*)d_in[2];   // [128, 256]
    float* out = (float*)d_out;               // [16384, 128]
    (void)in_sizes; (void)n_in; (void)out_size;

    gcn_fused<<<GRID, 256>>>(A, H, W, out);
}

// round 8
// speedup vs baseline: 1.3848x; 1.3848x over previous
#include <cuda_runtime.h>
#include <cuda_bf16.h>
#include <cstdint>

#define NN     16384
#define INF    256
#define OUTF   128
#define MAXNNZ 2048

// HW = H @ W^T (16384 x 128 fp32 = 8 MB, L2-resident)
__device__ float g_HW[NN * OUTF];

// ---------------------------------------------------------------------------
// HMMA helpers (sm_80-era mma.sync -- valid on sm_103 base target)
// ---------------------------------------------------------------------------
__device__ __forceinline__ void mma_bf16(float& c0, float& c1, float& c2, float& c3,
                                         uint32_t a0, uint32_t a1, uint32_t a2, uint32_t a3,
                                         uint32_t b0, uint32_t b1) {
    asm volatile(
        "mma.sync.aligned.m16n8k16.row.col.f32.bf16.bf16.f32 "
        "{%0,%1,%2,%3}, {%4,%5,%6,%7}, {%8,%9}, {%0,%1,%2,%3};"
        : "+f"(c0), "+f"(c1), "+f"(c2), "+f"(c3)
        : "r"(a0), "r"(a1), "r"(a2), "r"(a3), "r"(b0), "r"(b1));
}

__device__ __forceinline__ uint32_t bf16pair(float lo_elem, float hi_elem) {
    __nv_bfloat162 t = __floats2bfloat162_rn(lo_elem, hi_elem);  // .x = low 16b
    return *(uint32_t*)&t;
}
// hi/lo split of an fp32 value into two bf16s (captures ~16 mantissa bits)
__device__ __forceinline__ void split2(float v, float& hi, float& lo) {
    __nv_bfloat16 h = __float2bfloat16_rn(v);
    hi = __bfloat162float(h);
    lo = v - hi;
}

#define WSTRIDE 132   // u32 row stride; 132 % 32 == 4 -> conflict-free b-frag LDS

// ===========================================================================
// Kernel 1: g_HW = H @ W^T via mma.sync bf16 3-product split.
// Grid 128 CTAs x 256 thr (one wave). CTA: 128 H-rows x 128 out cols.
// Warp w: rows [row0 + w*16, +16), all 128 cols; acc = 16 n-frags x 4 fp32.
// W staged once per CTA into smem as packed bf16 k-pairs, hi & lo planes.
// ===========================================================================
__global__ __launch_bounds__(256) void hw_mma(const float* __restrict__ H,
                                              const float* __restrict__ W) {
    extern __shared__ uint32_t ws[];               // [2][128][WSTRIDE]
    uint32_t* ws_hi = ws;
    uint32_t* ws_lo = ws + OUTF * WSTRIDE;

    const int tid  = threadIdx.x;
    const int w    = tid >> 5;
    const int lane = tid & 31;
    const int row0 = blockIdx.x * 128;

    // ---- stage W (128 x 256 fp32) -> hi/lo bf16-pair planes ----
#pragma unroll
    for (int i = 0; i < (OUTF * INF / 2) / 256; i++) {   // 64 u32 per thread
        int idx = i * 256 + tid;                          // [0, 16384)
        int n   = idx >> 7;                               // out row
        int k2  = idx & 127;                              // k-pair index
        float2 e = *(const float2*)&W[(size_t)n * INF + k2 * 2];
        float h0, l0, h1, l1;
        split2(e.x, h0, l0);
        split2(e.y, h1, l1);
        ws_hi[n * WSTRIDE + k2] = bf16pair(h0, h1);
        ws_lo[n * WSTRIDE + k2] = bf16pair(l0, l1);
    }
    __syncthreads();

    // ---- mainloop: 16 k-steps of m16n8k16 over 16 n-frags ----
    float acc[16][4];
#pragma unroll
    for (int nf = 0; nf < 16; nf++)
#pragma unroll
        for (int j = 0; j < 4; j++) acc[nf][j] = 0.f;

    const int ra = row0 + w * 16 + (lane >> 2);    // A rows: ra, ra+8
    const int kc = (lane & 3) * 2;                 // A k cols: kc, kc+1 (+8)

#pragma unroll
    for (int ks = 0; ks < 16; ks++) {
        const int k0 = ks * 16 + kc;
        // A frag: a0=(ra,k0..k0+1) a1=(ra+8,k0..) a2=(ra,k0+8..) a3=(ra+8,k0+8..)
        float2 xa = *(const float2*)&H[(size_t)ra * INF + k0];
        float2 xb = *(const float2*)&H[(size_t)ra * INF + k0 + 8];
        float2 xc = *(const float2*)&H[(size_t)(ra + 8) * INF + k0];
        float2 xd = *(const float2*)&H[(size_t)(ra + 8) * INF + k0 + 8];

        float h0, l0, h1, l1;
        uint32_t ah[4], al[4];
        split2(xa.x, h0, l0); split2(xa.y, h1, l1);
        ah[0] = bf16pair(h0, h1); al[0] = bf16pair(l0, l1);
        split2(xc.x, h0, l0); split2(xc.y, h1, l1);
        ah[1] = bf16pair(h0, h1); al[1] = bf16pair(l0, l1);
        split2(xb.x, h0, l0); split2(xb.y, h1, l1);
        ah[2] = bf16pair(h0, h1); al[2] = bf16pair(l0, l1);
        split2(xd.x, h0, l0); split2(xd.y, h1, l1);
        ah[3] = bf16pair(h0, h1); al[3] = bf16pair(l0, l1);

        const int k2 = ks * 8 + (lane & 3);        // b-frag k-pair index
#pragma unroll
        for (int nf = 0; nf < 16; nf++) {
            const int n = nf * 8 + (lane >> 2);    // b-frag out col
            uint32_t bh0 = ws_hi[n * WSTRIDE + k2];
            uint32_t bh1 = ws_hi[n * WSTRIDE + k2 + 4];
            uint32_t bl0 = ws_lo[n * WSTRIDE + k2];
            uint32_t bl1 = ws_lo[n * WSTRIDE + k2 + 4];
            mma_bf16(acc[nf][0], acc[nf][1], acc[nf][2], acc[nf][3],
                     ah[0], ah[1], ah[2], ah[3], bh0, bh1);   // hi*hi
            mma_bf16(acc[nf][0], acc[nf][1], acc[nf][2], acc[nf][3],
                     ah[0], ah[1], ah[2], ah[3], bl0, bl1);   // hi*lo
            mma_bf16(acc[nf][0], acc[nf][1], acc[nf][2], acc[nf][3],
                     al[0], al[1], al[2], al[3], bh0, bh1);   // lo*hi
        }
    }

    // ---- epilogue: D rows = H-rows, cols = out features ----
    const int r0 = row0 + w * 16 + (lane >> 2);
#pragma unroll
    for (int nf = 0; nf < 16; nf++) {
        const int c0 = nf * 8 + (lane & 3) * 2;
        *(float2*)&g_HW[(size_t)r0 * OUTF + c0]       = make_float2(acc[nf][0], acc[nf][1]);
        *(float2*)&g_HW[(size_t)(r0 + 8) * OUTF + c0] = make_float2(acc[nf][2], acc[nf][3]);
    }
}

// ===========================================================================
// Kernel 2: R1 aggregate, verbatim (proven 85.9% DRAM / 6.8 TB/s).
// ===========================================================================
__global__ __launch_bounds__(256) void aggregate(const float* __restrict__ A,
                                                 float* __restrict__ out) {
    __shared__ int   s_idx[MAXNNZ];
    __shared__ int   s_cnt;
    __shared__ float s_red[OUTF];

    const int tid = threadIdx.x;
    const size_t row = blockIdx.x;

    if (tid == 0) s_cnt = 0;
    __syncthreads();

    const float4* Arow = (const float4*)(A + row * NN);
#pragma unroll
    for (int it = 0; it < NN / (256 * 4); it++) {
        int q = it * 256 + tid;
        float4 v = __ldcs(&Arow[q]);
        int base = q * 4;
        if (v.x != 0.f) { int p = atomicAdd(&s_cnt, 1); if (p < MAXNNZ) s_idx[p] = base;     }
        if (v.y != 0.f) { int p = atomicAdd(&s_cnt, 1); if (p < MAXNNZ) s_idx[p] = base + 1; }
        if (v.z != 0.f) { int p = atomicAdd(&s_cnt, 1); if (p < MAXNNZ) s_idx[p] = base + 2; }
        if (v.w != 0.f) { int p = atomicAdd(&s_cnt, 1); if (p < MAXNNZ) s_idx[p] = base + 3; }
    }
    __syncthreads();

    const int cnt = s_cnt;
    const int lim = cnt < MAXNNZ ? cnt : MAXNNZ;
    const int c = tid & 127;
    const int h = tid >> 7;

    float acc = 0.f;
    for (int k = h; k < lim; k += 2)
        acc += g_HW[(size_t)s_idx[k] * OUTF + c];

    if (h == 1) s_red[c] = acc;
    __syncthreads();
    if (h == 0) {
        float total = acc + s_red[c];
        out[row * OUTF + c] = total / (float)(cnt + 1);
    }
}

extern "C" void kernel_launch(void* const* d_in, const int* in_sizes, int n_in,
                              void* d_out, int out_size) {
    const float* A = (const float*)d_in[0];   // [16384, 16384]
    const float* H = (const float*)d_in[1];   // [16384, 256]
    const float* W = (const float*)d_in[2];   // [128, 256]
    float* out = (float*)d_out;               // [16384, 128]
    (void)in_sizes; (void)n_in; (void)out_size;

    const int wsm = 2 * OUTF * WSTRIDE * 4;   // 135168 B dynamic smem
    cudaFuncSetAttribute(hw_mma, cudaFuncAttributeMaxDynamicSharedMemorySize, wsm);
    hw_mma<<<NN / 128, 256, wsm>>>(H, W);
    aggregate<<<NN, 256>>>(A, out);
}

// round 10
// speedup vs baseline: 1.4394x; 1.0394x over previous
#include <cuda_runtime.h>
#include <cuda_bf16.h>
#include <cstdint>

#define NN     16384
#define INF    256
#define OUTF   128
#define MAXNNZ 2048

// HW = H @ W^T (16384 x 128 fp32 = 8 MB, L2-resident)
__device__ float g_HW[NN * OUTF];

// ---------------------------------------------------------------------------
// HMMA helpers (sm_80-era mma.sync -- valid on sm_103 base target)
// ---------------------------------------------------------------------------
__device__ __forceinline__ void mma_bf16(float& c0, float& c1, float& c2, float& c3,
                                         uint32_t a0, uint32_t a1, uint32_t a2, uint32_t a3,
                                         uint32_t b0, uint32_t b1) {
    asm volatile(
        "mma.sync.aligned.m16n8k16.row.col.f32.bf16.bf16.f32 "
        "{%0,%1,%2,%3}, {%4,%5,%6,%7}, {%8,%9}, {%0,%1,%2,%3};"
        : "+f"(c0), "+f"(c1), "+f"(c2), "+f"(c3)
        : "r"(a0), "r"(a1), "r"(a2), "r"(a3), "r"(b0), "r"(b1));
}

__device__ __forceinline__ uint32_t bf16pair(float lo_elem, float hi_elem) {
    __nv_bfloat162 t = __floats2bfloat162_rn(lo_elem, hi_elem);  // .x = low 16b
    return *(uint32_t*)&t;
}
__device__ __forceinline__ void split2(float v, float& hi, float& lo) {
    __nv_bfloat16 h = __float2bfloat16_rn(v);
    hi = __bfloat162float(h);
    lo = v - hi;
}

#define WSTRIDE 132   // u32 row stride; conflict-free b-frag LDS

// ===========================================================================
// Kernel 1: g_HW = H @ W^T via mma.sync bf16 3-product split (R8, proven).
// Triggers PDL completion at entry so aggregate's scan co-runs from t~0.
// ===========================================================================
__global__ __launch_bounds__(256) void hw_mma(const float* __restrict__ H,
                                              const float* __restrict__ W) {
#if __CUDA_ARCH__ >= 900
    cudaTriggerProgrammaticLaunchCompletion();
#endif
    extern __shared__ uint32_t ws[];               // [2][128][WSTRIDE]
    uint32_t* ws_hi = ws;
    uint32_t* ws_lo = ws + OUTF * WSTRIDE;

    const int tid  = threadIdx.x;
    const int w    = tid >> 5;
    const int lane = tid & 31;
    const int row0 = blockIdx.x * 128;

    // ---- stage W (128 x 256 fp32) -> hi/lo bf16-pair planes ----
#pragma unroll
    for (int i = 0; i < (OUTF * INF / 2) / 256; i++) {   // 64 u32 per thread
        int idx = i * 256 + tid;
        int n   = idx >> 7;
        int k2  = idx & 127;
        float2 e = *(const float2*)&W[(size_t)n * INF + k2 * 2];
        float h0, l0, h1, l1;
        split2(e.x, h0, l0);
        split2(e.y, h1, l1);
        ws_hi[n * WSTRIDE + k2] = bf16pair(h0, h1);
        ws_lo[n * WSTRIDE + k2] = bf16pair(l0, l1);
    }
    __syncthreads();

    float acc[16][4];
#pragma unroll
    for (int nf = 0; nf < 16; nf++)
#pragma unroll
        for (int j = 0; j < 4; j++) acc[nf][j] = 0.f;

    const int ra = row0 + w * 16 + (lane >> 2);    // A rows: ra, ra+8
    const int kc = (lane & 3) * 2;

#pragma unroll
    for (int ks = 0; ks < 16; ks++) {
        const int k0 = ks * 16 + kc;
        float2 xa = *(const float2*)&H[(size_t)ra * INF + k0];
        float2 xb = *(const float2*)&H[(size_t)ra * INF + k0 + 8];
        float2 xc = *(const float2*)&H[(size_t)(ra + 8) * INF + k0];
        float2 xd = *(const float2*)&H[(size_t)(ra + 8) * INF + k0 + 8];

        float h0, l0, h1, l1;
        uint32_t ah[4], al[4];
        split2(xa.x, h0, l0); split2(xa.y, h1, l1);
        ah[0] = bf16pair(h0, h1); al[0] = bf16pair(l0, l1);
        split2(xc.x, h0, l0); split2(xc.y, h1, l1);
        ah[1] = bf16pair(h0, h1); al[1] = bf16pair(l0, l1);
        split2(xb.x, h0, l0); split2(xb.y, h1, l1);
        ah[2] = bf16pair(h0, h1); al[2] = bf16pair(l0, l1);
        split2(xd.x, h0, l0); split2(xd.y, h1, l1);
        ah[3] = bf16pair(h0, h1); al[3] = bf16pair(l0, l1);

        const int k2 = ks * 8 + (lane & 3);
#pragma unroll
        for (int nf = 0; nf < 16; nf++) {
            const int n = nf * 8 + (lane >> 2);
            uint32_t bh0 = ws_hi[n * WSTRIDE + k2];
            uint32_t bh1 = ws_hi[n * WSTRIDE + k2 + 4];
            uint32_t bl0 = ws_lo[n * WSTRIDE + k2];
            uint32_t bl1 = ws_lo[n * WSTRIDE + k2 + 4];
            mma_bf16(acc[nf][0], acc[nf][1], acc[nf][2], acc[nf][3],
                     ah[0], ah[1], ah[2], ah[3], bh0, bh1);   // hi*hi
            mma_bf16(acc[nf][0], acc[nf][1], acc[nf][2], acc[nf][3],
                     ah[0], ah[1], ah[2], ah[3], bl0, bl1);   // hi*lo
            mma_bf16(acc[nf][0], acc[nf][1], acc[nf][2], acc[nf][3],
                     al[0], al[1], al[2], al[3], bh0, bh1);   // lo*hi
        }
    }

    const int r0 = row0 + w * 16 + (lane >> 2);
#pragma unroll
    for (int nf = 0; nf < 16; nf++) {
        const int c0 = nf * 8 + (lane & 3) * 2;
        *(float2*)&g_HW[(size_t)r0 * OUTF + c0]       = make_float2(acc[nf][0], acc[nf][1]);
        *(float2*)&g_HW[(size_t)(r0 + 8) * OUTF + c0] = make_float2(acc[nf][2], acc[nf][3]);
    }
}

// ===========================================================================
// Kernel 2: R1 aggregate + grid-dependency sync moved AFTER the A-scan.
// Scan phase needs no hw_mma results -> overlaps the GEMM under PDL.
// ===========================================================================
__global__ __launch_bounds__(256) void aggregate(const float* __restrict__ A,
                                                 float* __restrict__ out) {
    __shared__ int   s_idx[MAXNNZ];
    __shared__ int   s_cnt;
    __shared__ float s_red[OUTF];

    const int tid = threadIdx.x;
    const size_t row = blockIdx.x;

    if (tid == 0) s_cnt = 0;
    __syncthreads();

    const float4* Arow = (const float4*)(A + row * NN);
#pragma unroll
    for (int it = 0; it < NN / (256 * 4); it++) {
        int q = it * 256 + tid;
        float4 v = __ldcs(&Arow[q]);
        int base = q * 4;
        if (v.x != 0.f) { int p = atomicAdd(&s_cnt, 1); if (p < MAXNNZ) s_idx[p] = base;     }
        if (v.y != 0.f) { int p = atomicAdd(&s_cnt, 1); if (p < MAXNNZ) s_idx[p] = base + 1; }
        if (v.z != 0.f) { int p = atomicAdd(&s_cnt, 1); if (p < MAXNNZ) s_idx[p] = base + 2; }
        if (v.w != 0.f) { int p = atomicAdd(&s_cnt, 1); if (p < MAXNNZ) s_idx[p] = base + 3; }
    }
    __syncthreads();

#if __CUDA_ARCH__ >= 900
    cudaGridDependencySynchronize();   // g_HW ready past this point
#endif

    const int cnt = s_cnt;
    const int lim = cnt < MAXNNZ ? cnt : MAXNNZ;
    const int c = tid & 127;
    const int h = tid >> 7;

    float acc = 0.f;
    for (int k = h; k < lim; k += 2)
        acc += g_HW[(size_t)s_idx[k] * OUTF + c];

    if (h == 1) s_red[c] = acc;
    __syncthreads();
    if (h == 0) {
        float total = acc + s_red[c];
        out[row * OUTF + c] = total / (float)(cnt + 1);
    }
}

extern "C" void kernel_launch(void* const* d_in, const int* in_sizes, int n_in,
                              void* d_out, int out_size) {
    const float* A = (const float*)d_in[0];   // [16384, 16384]
    const float* H = (const float*)d_in[1];   // [16384, 256]
    const float* W = (const float*)d_in[2];   // [128, 256]
    float* out = (float*)d_out;               // [16384, 128]
    (void)in_sizes; (void)n_in; (void)out_size;

    const int wsm = 2 * OUTF * WSTRIDE * 4;   // 135168 B dynamic smem
    cudaFuncSetAttribute(hw_mma, cudaFuncAttributeMaxDynamicSharedMemorySize, wsm);
    hw_mma<<<NN / 128, 256, wsm>>>(H, W);

    // Programmatic Dependent Launch: aggregate may begin while hw_mma runs;
    // in-kernel cudaGridDependencySynchronize() gates the g_HW consumption.
    cudaLaunchConfig_t cfg = {};
    cfg.gridDim  = dim3(NN, 1, 1);
    cfg.blockDim = dim3(256, 1, 1);
    cfg.dynamicSmemBytes = 0;
    cudaLaunchAttribute attr[1];
    attr[0].id = cudaLaunchAttributeProgrammaticStreamSerialization;
    attr[0].val.programmaticStreamSerializationAllowed = 1;
    cfg.attrs    = attr;
    cfg.numAttrs = 1;
    cudaLaunchKernelEx(&cfg, aggregate, A, out);
}

// round 11
// speedup vs baseline: 1.4400x; 1.0004x over previous
#include <cuda_runtime.h>
#include <cuda_bf16.h>
#include <cstdint>

#define NN     16384
#define INF    256
#define OUTF   128
#define MAXNNZ 2048

// HW = H @ W^T (16384 x 128 fp32 = 8 MB, L2-resident)
__device__ float g_HW[NN * OUTF];

// ---------------------------------------------------------------------------
// HMMA helpers (sm_80-era mma.sync -- valid on sm_103 base target)
// ---------------------------------------------------------------------------
__device__ __forceinline__ void mma_bf16(float& c0, float& c1, float& c2, float& c3,
                                         uint32_t a0, uint32_t a1, uint32_t a2, uint32_t a3,
                                         uint32_t b0, uint32_t b1) {
    asm volatile(
        "mma.sync.aligned.m16n8k16.row.col.f32.bf16.bf16.f32 "
        "{%0,%1,%2,%3}, {%4,%5,%6,%7}, {%8,%9}, {%0,%1,%2,%3};"
        : "+f"(c0), "+f"(c1), "+f"(c2), "+f"(c3)
        : "r"(a0), "r"(a1), "r"(a2), "r"(a3), "r"(b0), "r"(b1));
}

__device__ __forceinline__ uint32_t bf16pair(float lo_elem, float hi_elem) {
    __nv_bfloat162 t = __floats2bfloat162_rn(lo_elem, hi_elem);  // .x = low 16b
    return *(uint32_t*)&t;
}
__device__ __forceinline__ void split2(float v, float& hi, float& lo) {
    __nv_bfloat16 h = __float2bfloat16_rn(v);
    hi = __bfloat162float(h);
    lo = v - hi;
}

// b-frag table: per n-row, 68 uint4 (16 ks x 4 q, padded 64 -> 68).
// n-stride = 272 words; 272 mod 32 == 16 -> LDS.128 phases conflict-free.
#define NSTRIDE_Q 68   // uint4 per n row

// ===========================================================================
// Kernel 1: g_HW = H @ W^T via mma.sync bf16 3-product split.
// W prepacked in smem as uint4 {bh0,bh1,bl0,bl1} per (n,ks,q): one LDS.128
// per mma-triple instead of 4 LDS.32. PDL-triggers at entry.
// ===========================================================================
__global__ __launch_bounds__(256) void hw_mma(const float* __restrict__ H,
                                              const float* __restrict__ W) {
#if __CUDA_ARCH__ >= 900
    cudaTriggerProgrammaticLaunchCompletion();
#endif
    extern __shared__ uint4 wsq[];                 // [128][NSTRIDE_Q]

    const int tid  = threadIdx.x;
    const int w    = tid >> 5;
    const int lane = tid & 31;
    const int row0 = blockIdx.x * 128;

    // ---- stage W: for (n, ks, q) pack {hi(k2),hi(k2+4),lo(k2),lo(k2+4)} ----
    // k2 = ks*8 + q (k-pair index); element cols = k2*2, k2*2+1.
#pragma unroll
    for (int i = 0; i < (OUTF * 16 * 4) / 256; i++) {    // 32 uint4 / thread
        int idx = i * 256 + tid;                          // [0, 8192)
        int n   = idx >> 6;
        int ks  = (idx >> 2) & 15;
        int q   = idx & 3;
        int k2  = ks * 8 + q;
        float2 e0 = *(const float2*)&W[(size_t)n * INF + k2 * 2];
        float2 e1 = *(const float2*)&W[(size_t)n * INF + (k2 + 4) * 2];
        float h0, l0, h1, l1, h2, l2, h3, l3;
        split2(e0.x, h0, l0); split2(e0.y, h1, l1);
        split2(e1.x, h2, l2); split2(e1.y, h3, l3);
        uint4 v;
        v.x = bf16pair(h0, h1);   // bh0
        v.y = bf16pair(h2, h3);   // bh1
        v.z = bf16pair(l0, l1);   // bl0
        v.w = bf16pair(l2, l3);   // bl1
        wsq[n * NSTRIDE_Q + ks * 4 + q] = v;
    }
    __syncthreads();

    float acc[16][4];
#pragma unroll
    for (int nf = 0; nf < 16; nf++)
#pragma unroll
        for (int j = 0; j < 4; j++) acc[nf][j] = 0.f;

    const int ra = row0 + w * 16 + (lane >> 2);    // A rows: ra, ra+8
    const int kc = (lane & 3) * 2;

#pragma unroll
    for (int ks = 0; ks < 16; ks++) {
        const int k0 = ks * 16 + kc;
        float2 xa = *(const float2*)&H[(size_t)ra * INF + k0];
        float2 xb = *(const float2*)&H[(size_t)ra * INF + k0 + 8];
        float2 xc = *(const float2*)&H[(size_t)(ra + 8) * INF + k0];
        float2 xd = *(const float2*)&H[(size_t)(ra + 8) * INF + k0 + 8];

        float h0, l0, h1, l1;
        uint32_t ah[4], al[4];
        split2(xa.x, h0, l0); split2(xa.y, h1, l1);
        ah[0] = bf16pair(h0, h1); al[0] = bf16pair(l0, l1);
        split2(xc.x, h0, l0); split2(xc.y, h1, l1);
        ah[1] = bf16pair(h0, h1); al[1] = bf16pair(l0, l1);
        split2(xb.x, h0, l0); split2(xb.y, h1, l1);
        ah[2] = bf16pair(h0, h1); al[2] = bf16pair(l0, l1);
        split2(xd.x, h0, l0); split2(xd.y, h1, l1);
        ah[3] = bf16pair(h0, h1); al[3] = bf16pair(l0, l1);

        const int qoff = ks * 4 + (lane & 3);
#pragma unroll
        for (int nf = 0; nf < 16; nf++) {
            const int n = nf * 8 + (lane >> 2);
            uint4 b = wsq[n * NSTRIDE_Q + qoff];   // one LDS.128
            mma_bf16(acc[nf][0], acc[nf][1], acc[nf][2], acc[nf][3],
                     ah[0], ah[1], ah[2], ah[3], b.x, b.y);   // hi*hi
            mma_bf16(acc[nf][0], acc[nf][1], acc[nf][2], acc[nf][3],
                     ah[0], ah[1], ah[2], ah[3], b.z, b.w);   // hi*lo
            mma_bf16(acc[nf][0], acc[nf][1], acc[nf][2], acc[nf][3],
                     al[0], al[1], al[2], al[3], b.x, b.y);   // lo*hi
        }
    }

    const int r0 = row0 + w * 16 + (lane >> 2);
#pragma unroll
    for (int nf = 0; nf < 16; nf++) {
        const int c0 = nf * 8 + (lane & 3) * 2;
        *(float2*)&g_HW[(size_t)r0 * OUTF + c0]       = make_float2(acc[nf][0], acc[nf][1]);
        *(float2*)&g_HW[(size_t)(r0 + 8) * OUTF + c0] = make_float2(acc[nf][2], acc[nf][3]);
    }
}

// ===========================================================================
// Kernel 2: R1 aggregate + grid-dependency sync AFTER the A-scan (R10, proven).
// ===========================================================================
__global__ __launch_bounds__(256) void aggregate(const float* __restrict__ A,
                                                 float* __restrict__ out) {
    __shared__ int   s_idx[MAXNNZ];
    __shared__ int   s_cnt;
    __shared__ float s_red[OUTF];

    const int tid = threadIdx.x;
    const size_t row = blockIdx.x;

    if (tid == 0) s_cnt = 0;
    __syncthreads();

    const float4* Arow = (const float4*)(A + row * NN);
#pragma unroll
    for (int it = 0; it < NN / (256 * 4); it++) {
        int q = it * 256 + tid;
        float4 v = __ldcs(&Arow[q]);
        int base = q * 4;
        if (v.x != 0.f) { int p = atomicAdd(&s_cnt, 1); if (p < MAXNNZ) s_idx[p] = base;     }
        if (v.y != 0.f) { int p = atomicAdd(&s_cnt, 1); if (p < MAXNNZ) s_idx[p] = base + 1; }
        if (v.z != 0.f) { int p = atomicAdd(&s_cnt, 1); if (p < MAXNNZ) s_idx[p] = base + 2; }
        if (v.w != 0.f) { int p = atomicAdd(&s_cnt, 1); if (p < MAXNNZ) s_idx[p] = base + 3; }
    }
    __syncthreads();

#if __CUDA_ARCH__ >= 900
    cudaGridDependencySynchronize();   // g_HW ready past this point
#endif

    const int cnt = s_cnt;
    const int lim = cnt < MAXNNZ ? cnt : MAXNNZ;
    const int c = tid & 127;
    const int h = tid >> 7;

    float acc = 0.f;
    for (int k = h; k < lim; k += 2)
        acc += g_HW[(size_t)s_idx[k] * OUTF + c];

    if (h == 1) s_red[c] = acc;
    __syncthreads();
    if (h == 0) {
        float total = acc + s_red[c];
        out[row * OUTF + c] = total / (float)(cnt + 1);
    }
}

extern "C" void kernel_launch(void* const* d_in, const int* in_sizes, int n_in,
                              void* d_out, int out_size) {
    const float* A = (const float*)d_in[0];   // [16384, 16384]
    const float* H = (const float*)d_in[1];   // [16384, 256]
    const float* W = (const float*)d_in[2];   // [128, 256]
    float* out = (float*)d_out;               // [16384, 128]
    (void)in_sizes; (void)n_in; (void)out_size;

    const int wsm = OUTF * NSTRIDE_Q * 16;    // 139264 B dynamic smem
    cudaFuncSetAttribute(hw_mma, cudaFuncAttributeMaxDynamicSharedMemorySize, wsm);
    hw_mma<<<NN / 128, 256, wsm>>>(H, W);

    // Programmatic Dependent Launch: aggregate begins while hw_mma runs;
    // in-kernel cudaGridDependencySynchronize() gates g_HW consumption.
    cudaLaunchConfig_t cfg = {};
    cfg.gridDim  = dim3(NN, 1, 1);
    cfg.blockDim = dim3(256, 1, 1);
    cfg.dynamicSmemBytes = 0;
    cudaLaunchAttribute attr[1];
    attr[0].id = cudaLaunchAttributeProgrammaticStreamSerialization;
    attr[0].val.programmaticStreamSerializationAllowed = 1;
    cfg.attrs    = attr;
    cfg.numAttrs = 1;
    cudaLaunchKernelEx(&cfg, aggregate, A, out);
}